// round 1
// baseline (speedup 1.0000x reference)
#include <cuda_runtime.h>
#include <math_constants.h>
#include <cstdint>

// Problem constants (fixed shapes from reference)
#define SS      128     // src_len
#define BB      64      // batch
#define HH      512     // hidden
#define VV      100     // vocab
#define TSTEPS  31      // T-1 decode steps
#define G3H     1536    // 3*H
#define NTH     256     // threads per block

// ---------------- persistent scratch (no allocations allowed) ----------------
__device__ float g_h[2][BB * HH];      // hidden double buffer
__device__ float g_ctx[BB * HH];       // attention context
__device__ float g_x[BB * HH];         // relu(comb) output
__device__ float g_gh[BB * G3H];       // h @ W_hh^T + b_hh
__device__ unsigned g_barcnt = 0;
__device__ unsigned g_bargen = 0;

__device__ __forceinline__ float warp_sum(float v) {
#pragma unroll
    for (int o = 16; o; o >>= 1) v += __shfl_xor_sync(0xffffffffu, v, o);
    return v;
}

__device__ __forceinline__ float dot4(float4 a, float4 b) {
    return a.x * b.x + a.y * b.y + a.z * b.z + a.w * b.w;
}

// Sense-reversing grid barrier (grid == one wave, all CTAs resident).
__device__ __forceinline__ void gridbar(int nb) {
    __syncthreads();
    if (threadIdx.x == 0) {
        __threadfence();
        unsigned gen = *((volatile unsigned*)&g_bargen);
        unsigned old = atomicAdd(&g_barcnt, 1u);
        if (old == (unsigned)(nb - 1)) {
            atomicExch(&g_barcnt, 0u);
            atomicExch(&g_bargen, gen + 1u);
        } else {
            while (*((volatile unsigned*)&g_bargen) == gen) { __nanosleep(64); }
        }
        __threadfence();
    }
    __syncthreads();
}

// logits row + log_softmax for one batch element (block-collective)
__device__ __forceinline__ void do_logits(
    const float* __restrict__ hrow,     // &h[b*HH]
    const float* __restrict__ W_out, const float* __restrict__ b_out,
    float* __restrict__ outp,           // &out[b*TSTEPS*VV + slot*VV]
    float* sh_h, float* sh_l, float* sh_scalar)
{
    const int tid = threadIdx.x, wid = tid >> 5, lane = tid & 31;
    for (int i = tid; i < HH; i += NTH) sh_h[i] = hrow[i];
    __syncthreads();
    const float4* hp = (const float4*)sh_h;
    for (int v = wid; v < VV; v += NTH / 32) {
        const float4* wr = (const float4*)(W_out + (size_t)v * HH);
        float acc = 0.f;
#pragma unroll
        for (int c = 0; c < 4; c++) {
            int k = lane + 32 * c;
            acc += dot4(wr[k], hp[k]);
        }
        acc = warp_sum(acc);
        if (lane == 0) sh_l[v] = acc + b_out[v];
    }
    __syncthreads();
    if (wid == 0) {
        float v0 = sh_l[lane];
        float v1 = sh_l[lane + 32];
        float v2 = sh_l[lane + 64];
        bool ok3 = (lane < VV - 96);
        float v3 = ok3 ? sh_l[lane + 96] : -CUDART_INF_F;
        float m = fmaxf(fmaxf(v0, v1), fmaxf(v2, v3));
#pragma unroll
        for (int o = 16; o; o >>= 1) m = fmaxf(m, __shfl_xor_sync(0xffffffffu, m, o));
        float s = expf(v0 - m) + expf(v1 - m) + expf(v2 - m) + (ok3 ? expf(v3 - m) : 0.f);
        s = warp_sum(s);
        if (lane == 0) sh_scalar[0] = m + logf(s);
    }
    __syncthreads();
    float lse = sh_scalar[0];
    for (int v = tid; v < VV; v += NTH) outp[v] = sh_l[v] - lse;
    __syncthreads();
}

__global__ void __launch_bounds__(NTH)
bahdanau_kernel(
    const float* __restrict__ enc,    const float* __restrict__ W_emb,
    const float* __restrict__ W_comb, const float* __restrict__ b_comb,
    const float* __restrict__ W_ih,   const float* __restrict__ W_hh,
    const float* __restrict__ b_ih,   const float* __restrict__ b_hh,
    const float* __restrict__ W_out,  const float* __restrict__ b_out,
    const float* __restrict__ w_vat,  const float* __restrict__ b_vat,
    const int* __restrict__ tgt, float* __restrict__ out, int nb)
{
    const int bid = blockIdx.x;
    const int tid = threadIdx.x;
    const int wid = tid >> 5, lane = tid & 31;

    __shared__ float sh_h[HH];
    __shared__ float sh_w[HH];
    __shared__ float sh_sc[SS];
    __shared__ float sh_scalar[1];

    // zero initial hidden state (every launch: deterministic)
    for (int i = bid * NTH + tid; i < BB * HH; i += nb * NTH) g_h[0][i] = 0.f;
    gridbar(nb);

    for (int t = 0; t < TSTEPS; t++) {
        const float* hcur = g_h[t & 1];
        float* hnext = g_h[(t + 1) & 1];

        // ================= Phase A =================
        if (bid < BB) {
            // ---- attention for batch element b (block-local) ----
            const int b = bid;
            for (int i = tid; i < HH; i += NTH) {
                sh_h[i] = hcur[b * HH + i];
                sh_w[i] = w_vat[i];
            }
            __syncthreads();
            const float bv = b_vat[0];
            const float4* hp = (const float4*)sh_h;
            const float4* wp = (const float4*)sh_w;
            for (int s = wid; s < SS; s += NTH / 32) {
                const float4* ep = (const float4*)(enc + ((size_t)s * BB + b) * HH);
                float acc = 0.f;
#pragma unroll
                for (int c = 0; c < 4; c++) {
                    int k = lane + 32 * c;
                    float4 e = ep[k], h4 = hp[k], w4 = wp[k];
                    acc += tanhf(e.x + h4.x) * w4.x;
                    acc += tanhf(e.y + h4.y) * w4.y;
                    acc += tanhf(e.z + h4.z) * w4.z;
                    acc += tanhf(e.w + h4.w) * w4.w;
                }
                acc = warp_sum(acc);
                if (lane == 0) sh_sc[s] = acc + bv;
            }
            __syncthreads();
            if (wid == 0) {
                float v0 = sh_sc[lane], v1 = sh_sc[lane + 32];
                float v2 = sh_sc[lane + 64], v3 = sh_sc[lane + 96];
                float m = fmaxf(fmaxf(v0, v1), fmaxf(v2, v3));
#pragma unroll
                for (int o = 16; o; o >>= 1) m = fmaxf(m, __shfl_xor_sync(0xffffffffu, m, o));
                float e0 = expf(v0 - m), e1 = expf(v1 - m), e2 = expf(v2 - m), e3 = expf(v3 - m);
                float ssum = warp_sum(e0 + e1 + e2 + e3);
                float inv = 1.f / ssum;
                sh_sc[lane] = e0 * inv; sh_sc[lane + 32] = e1 * inv;
                sh_sc[lane + 64] = e2 * inv; sh_sc[lane + 96] = e3 * inv;
            }
            __syncthreads();
            {
                // ctx[b, :] = sum_s attn[s] * enc[s, b, :]
                const int h0 = tid * 2;  // 256 threads * 2 = 512 columns
                const float* base = enc + (size_t)b * HH + h0;
                float a0 = 0.f, a1 = 0.f;
#pragma unroll 4
                for (int s = 0; s < SS; s++) {
                    float w = sh_sc[s];
                    float2 e = *(const float2*)(base + (size_t)s * (BB * HH));
                    a0 += w * e.x; a1 += w * e.y;
                }
                g_ctx[b * HH + h0] = a0;
                g_ctx[b * HH + h0 + 1] = a1;
            }
        } else {
            // ---- previous-step logits (don't feed the recurrence) ----
            if (bid < 2 * BB && t > 0) {
                const int b = bid - BB;
                do_logits(hcur + (size_t)b * HH, W_out, b_out,
                          out + (size_t)b * TSTEPS * VV + (size_t)(t - 1) * VV,
                          sh_h, sh_sc, sh_scalar);
            }
            // ---- gh = h @ W_hh^T + b_hh (depends only on h) ----
            const int nbg = nb - BB;
            for (int pair = (bid - BB) * (NTH / 32) + wid; pair < G3H * BB;
                 pair += nbg * (NTH / 32)) {
                const int j = pair >> 6, b = pair & 63;
                const float4* wr  = (const float4*)(W_hh + (size_t)j * HH);
                const float4* hp2 = (const float4*)(hcur + (size_t)b * HH);
                float acc = 0.f;
#pragma unroll
                for (int c = 0; c < 4; c++) {
                    int k = lane + 32 * c;
                    acc += dot4(wr[k], hp2[k]);
                }
                acc = warp_sum(acc);
                if (lane == 0) g_gh[b * G3H + j] = acc + b_hh[j];
            }
        }
        gridbar(nb);

        // ================= Phase B: x = relu([emb|ctx] @ W_comb^T + b_comb) ==
        {
            const int gw = bid * (NTH / 32) + wid, gstr = nb * (NTH / 32);
            for (int pair = gw; pair < BB * HH; pair += gstr) {
                const int j = pair >> 6, b = pair & 63;
                const int sym = tgt[t * BB + b];
                const float4* er = (const float4*)(W_emb + (size_t)sym * HH);
                const float4* cr = (const float4*)(g_ctx + (size_t)b * HH);
                const float4* wr = (const float4*)(W_comb + (size_t)j * (2 * HH));
                float acc = 0.f;
#pragma unroll
                for (int c = 0; c < 4; c++) {
                    int k = lane + 32 * c;
                    acc += dot4(er[k], wr[k]);
                    acc += dot4(cr[k], wr[128 + k]);
                }
                acc = warp_sum(acc);
                if (lane == 0) g_x[b * HH + j] = fmaxf(acc + b_comb[j], 0.f);
            }
        }
        gridbar(nb);

        // ================= Phase C: gi dots + GRU gates + h_new =============
        {
            const int gw = bid * (NTH / 32) + wid, gstr = nb * (NTH / 32);
            for (int pair = gw; pair < BB * HH; pair += gstr) {
                const int i = pair >> 6, b = pair & 63;
                const float4* xr   = (const float4*)(g_x + (size_t)b * HH);
                const float4* wr_r = (const float4*)(W_ih + (size_t)i * HH);
                const float4* wr_z = (const float4*)(W_ih + (size_t)(i + HH) * HH);
                const float4* wr_n = (const float4*)(W_ih + (size_t)(i + 2 * HH) * HH);
                float ar = 0.f, az = 0.f, an = 0.f;
#pragma unroll
                for (int c = 0; c < 4; c++) {
                    int k = lane + 32 * c;
                    float4 x4 = xr[k];
                    ar += dot4(x4, wr_r[k]);
                    az += dot4(x4, wr_z[k]);
                    an += dot4(x4, wr_n[k]);
                }
                ar = warp_sum(ar); az = warp_sum(az); an = warp_sum(an);
                if (lane == 0) {
                    const float* ghb = g_gh + b * G3H;
                    float gr = ar + b_ih[i] + ghb[i];
                    float gz = az + b_ih[i + HH] + ghb[i + HH];
                    float gn = an + b_ih[i + 2 * HH];
                    float r = 1.f / (1.f + expf(-gr));
                    float z = 1.f / (1.f + expf(-gz));
                    float n = tanhf(gn + r * ghb[i + 2 * HH]);
                    hnext[b * HH + i] = (1.f - z) * n + z * hcur[b * HH + i];
                }
            }
        }
        gridbar(nb);
    }

    // final logits (slot TSTEPS-1) from last h_new = g_h[TSTEPS & 1]
    if (bid >= BB && bid < 2 * BB) {
        const int b = bid - BB;
        do_logits(g_h[TSTEPS & 1] + (size_t)b * HH, W_out, b_out,
                  out + (size_t)b * TSTEPS * VV + (size_t)(TSTEPS - 1) * VV,
                  sh_h, sh_sc, sh_scalar);
    }
}

extern "C" void kernel_launch(void* const* d_in, const int* in_sizes, int n_in,
                              void* d_out, int out_size) {
    const float* enc    = (const float*)d_in[0];
    const float* W_emb  = (const float*)d_in[1];
    const float* W_comb = (const float*)d_in[2];
    const float* b_comb = (const float*)d_in[3];
    const float* W_ih   = (const float*)d_in[4];
    const float* W_hh   = (const float*)d_in[5];
    const float* b_ih   = (const float*)d_in[6];
    const float* b_hh   = (const float*)d_in[7];
    const float* W_out  = (const float*)d_in[8];
    const float* b_out  = (const float*)d_in[9];
    const float* w_vat  = (const float*)d_in[10];
    const float* b_vat  = (const float*)d_in[11];
    const int*   tgt    = (const int*)d_in[12];
    float* out = (float*)d_out;

    int dev = 0;
    cudaGetDevice(&dev);
    int sm = 148;
    cudaDeviceGetAttribute(&sm, cudaDevAttrMultiProcessorCount, dev);
    int nb = sm < 148 ? sm : 148;   // one wave: every CTA resident -> barrier is safe

    bahdanau_kernel<<<nb, NTH>>>(enc, W_emb, W_comb, b_comb, W_ih, W_hh,
                                 b_ih, b_hh, W_out, b_out, w_vat, b_vat,
                                 tgt, out, nb);
}

// round 3
// speedup vs baseline: 2.6675x; 2.6675x over previous
#include <cuda_runtime.h>
#include <math_constants.h>
#include <cstdint>

#define SS      128
#define BB      64
#define HH      512
#define VV      100
#define TSTEPS  31      // T-1 decode steps
#define G3H     1536
#define NTH     256
#define NB      148     // grid size (all resident: 256thr/10KB smem -> always fits)

// ---------------- persistent scratch ----------------
__device__ float g_hT[2][HH * BB];      // hidden, transposed [h][b]
__device__ float g_ctxT[HH * BB];       // context, transposed
__device__ float g_xp[2][HH * BB];      // comb partial sums [j][b]
__device__ float g_gh[G3H * BB];        // h @ W_hh^T + b_hh   [j][b]
__device__ float g_gi[G3H * BB];        // x @ W_ih^T + b_ih   [j][b]
__device__ float g_lg[VV * BB];         // raw logits [v][b]
__device__ unsigned g_barcnt = 0;
__device__ unsigned g_bargen = 0;

union SmemU {
    struct { float W[32][17]; float A[32][64]; } g;
    struct { float h[HH]; float w[HH]; float sc[SS]; } a;
};

__device__ __forceinline__ float warp_sum(float v) {
#pragma unroll
    for (int o = 16; o; o >>= 1) v += __shfl_xor_sync(0xffffffffu, v, o);
    return v;
}
__device__ __forceinline__ float warp_max(float v) {
#pragma unroll
    for (int o = 16; o; o >>= 1) v = fmaxf(v, __shfl_xor_sync(0xffffffffu, v, o));
    return v;
}
__device__ __forceinline__ float fast_tanh(float x) {
    float r;
    asm("tanh.approx.f32 %0, %1;" : "=f"(r) : "f"(x));
    return r;
}

// Sense-reversing grid barrier (all CTAs resident).
__device__ __forceinline__ void gridbar() {
    __syncthreads();
    if (threadIdx.x == 0) {
        __threadfence();
        unsigned gen = *((volatile unsigned*)&g_bargen);
        unsigned old = atomicAdd(&g_barcnt, 1u);
        if (old == NB - 1) {
            atomicExch(&g_barcnt, 0u);
            atomicExch(&g_bargen, gen + 1u);
        } else {
            while (*((volatile unsigned*)&g_bargen) == gen) { __nanosleep(64); }
        }
        __threadfence();
    }
    __syncthreads();
}

// ---------------------------------------------------------------------------
// Tiled GEMM: C[j0..j0+15][0..63] = W[j][k] * A[k][b], K = 512, Kc = 32.
// mode 0: A from transposed activation array A0 ([512][64], cross-block -> ldcg)
// mode 1: A[k][b] = W_emb[syms[b]][k]  (read-only input, plain loads)
// mode 2: A[k][b] = relu(A0[k][b] + A1[k][b] + xbias[k])   (cross-block -> ldcg)
// biasC: optional per-row bias added at epilogue. rowlim guards ragged M.
// ---------------------------------------------------------------------------
__device__ void gemm_tile(SmemU* sm,
                          const float* __restrict__ W, int ldw, int j0, int rowlim,
                          int mode, const float* __restrict__ A0,
                          const float* __restrict__ A1,
                          const float* __restrict__ xbias,
                          const int* __restrict__ syms,
                          const float* __restrict__ biasC,
                          float* __restrict__ Cout)
{
    const int tid = threadIdx.x;
    const int tx = tid & 15;      // j within tile (compute)
    const int ty = tid >> 4;      // b-group (compute), b0 = ty*4
    float acc0 = 0.f, acc1 = 0.f, acc2 = 0.f, acc3 = 0.f;

    for (int kc = 0; kc < HH; kc += 32) {
        // ---- load W tile (16 rows x 32 k) ----
        {
            int j = tid >> 4;                 // 0..15
            int kk = (tid & 15) * 2;          // 0..30
            int row = j0 + j;
            int r = row < rowlim ? row : rowlim - 1;
            const float2 w2 = *(const float2*)(W + (size_t)r * ldw + kc + kk);
            sm->g.W[kk][j]     = w2.x;
            sm->g.W[kk + 1][j] = w2.y;
        }
        // ---- load A tile (32 k x 64 b) ----
        if (mode == 0) {
            const float4* src = (const float4*)(A0 + (size_t)kc * BB);
            float4* dst = (float4*)&sm->g.A[0][0];
            dst[tid]       = __ldcg(&src[tid]);
            dst[tid + 256] = __ldcg(&src[tid + 256]);
        } else if (mode == 1) {
            int b = tid >> 2;
            int kg = (tid & 3) * 8;
            const float* src = A0 + (size_t)syms[b] * HH + kc + kg;
            float4 v0 = *(const float4*)src;
            float4 v1 = *(const float4*)(src + 4);
            sm->g.A[kg + 0][b] = v0.x; sm->g.A[kg + 1][b] = v0.y;
            sm->g.A[kg + 2][b] = v0.z; sm->g.A[kg + 3][b] = v0.w;
            sm->g.A[kg + 4][b] = v1.x; sm->g.A[kg + 5][b] = v1.y;
            sm->g.A[kg + 6][b] = v1.z; sm->g.A[kg + 7][b] = v1.w;
        } else {
            int e = tid * 8;                  // 8 consecutive (k*64+b), same k
            int k = e >> 6;
            float bv = xbias[kc + k];
            float4 u0 = __ldcg((const float4*)(A0 + (size_t)kc * BB + e));
            float4 u1 = __ldcg((const float4*)(A0 + (size_t)kc * BB + e + 4));
            float4 v0 = __ldcg((const float4*)(A1 + (size_t)kc * BB + e));
            float4 v1 = __ldcg((const float4*)(A1 + (size_t)kc * BB + e + 4));
            float* dst = &sm->g.A[0][0] + e;
            dst[0] = fmaxf(u0.x + v0.x + bv, 0.f);
            dst[1] = fmaxf(u0.y + v0.y + bv, 0.f);
            dst[2] = fmaxf(u0.z + v0.z + bv, 0.f);
            dst[3] = fmaxf(u0.w + v0.w + bv, 0.f);
            dst[4] = fmaxf(u1.x + v1.x + bv, 0.f);
            dst[5] = fmaxf(u1.y + v1.y + bv, 0.f);
            dst[6] = fmaxf(u1.z + v1.z + bv, 0.f);
            dst[7] = fmaxf(u1.w + v1.w + bv, 0.f);
        }
        __syncthreads();
#pragma unroll
        for (int k = 0; k < 32; k++) {
            float w = sm->g.W[k][tx];
            float4 a = *(const float4*)&sm->g.A[k][ty << 2];
            acc0 = fmaf(w, a.x, acc0);
            acc1 = fmaf(w, a.y, acc1);
            acc2 = fmaf(w, a.z, acc2);
            acc3 = fmaf(w, a.w, acc3);
        }
        __syncthreads();
    }
    int row = j0 + tx;
    if (row < rowlim) {
        float bb = biasC ? biasC[row] : 0.f;
        float4 r4 = make_float4(acc0 + bb, acc1 + bb, acc2 + bb, acc3 + bb);
        *(float4*)(Cout + (size_t)row * BB + (ty << 2)) = r4;
    }
}

// ---------------------------------------------------------------------------
// Bahdanau attention for batch element b (block-collective).
// ---------------------------------------------------------------------------
__device__ void attention_block(SmemU* sm, int b,
                                const float* __restrict__ enc,
                                const float* __restrict__ w_vat,
                                const float* __restrict__ b_vat,
                                const float* __restrict__ hT,
                                float* __restrict__ ctxT)
{
    const int tid = threadIdx.x, wid = tid >> 5, lane = tid & 31;
    for (int i = tid; i < HH; i += NTH) {
        sm->a.h[i] = __ldcg(&hT[i * BB + b]);
        sm->a.w[i] = w_vat[i];
    }
    __syncthreads();
    const float bv = b_vat[0];
    const float4* hp = (const float4*)sm->a.h;
    const float4* wp = (const float4*)sm->a.w;
    for (int s = wid; s < SS; s += NTH / 32) {
        const float4* ep = (const float4*)(enc + ((size_t)s * BB + b) * HH);
        float acc = 0.f;
#pragma unroll
        for (int c = 0; c < 4; c++) {
            int k = lane + 32 * c;
            float4 e = ep[k], h4 = hp[k], w4 = wp[k];
            acc += fast_tanh(e.x + h4.x) * w4.x;
            acc += fast_tanh(e.y + h4.y) * w4.y;
            acc += fast_tanh(e.z + h4.z) * w4.z;
            acc += fast_tanh(e.w + h4.w) * w4.w;
        }
        acc = warp_sum(acc);
        if (lane == 0) sm->a.sc[s] = acc + bv;
    }
    __syncthreads();
    if (wid == 0) {
        float v0 = sm->a.sc[lane],      v1 = sm->a.sc[lane + 32];
        float v2 = sm->a.sc[lane + 64], v3 = sm->a.sc[lane + 96];
        float m = warp_max(fmaxf(fmaxf(v0, v1), fmaxf(v2, v3)));
        float e0 = expf(v0 - m), e1 = expf(v1 - m);
        float e2 = expf(v2 - m), e3 = expf(v3 - m);
        float inv = 1.f / warp_sum(e0 + e1 + e2 + e3);
        sm->a.sc[lane]      = e0 * inv; sm->a.sc[lane + 32] = e1 * inv;
        sm->a.sc[lane + 64] = e2 * inv; sm->a.sc[lane + 96] = e3 * inv;
    }
    __syncthreads();
    {
        const int h0 = tid * 2;
        const float* base = enc + (size_t)b * HH + h0;
        float a0 = 0.f, a1 = 0.f;
#pragma unroll 4
        for (int s = 0; s < SS; s++) {
            float wv = sm->a.sc[s];
            float2 e = *(const float2*)(base + (size_t)s * (BB * HH));
            a0 = fmaf(wv, e.x, a0);
            a1 = fmaf(wv, e.y, a1);
        }
        ctxT[h0 * BB + b]       = a0;
        ctxT[(h0 + 1) * BB + b] = a1;
    }
    __syncthreads();
}

// log-softmax of one raw-logit column b (one warp), write to out slot.
__device__ void lsm_row(int b, float* __restrict__ outp)
{
    const int lane = threadIdx.x & 31;
    float v0 = __ldcg(&g_lg[lane * BB + b]);
    float v1 = __ldcg(&g_lg[(lane + 32) * BB + b]);
    float v2 = __ldcg(&g_lg[(lane + 64) * BB + b]);
    bool ok3 = lane < (VV - 96);
    float v3 = ok3 ? __ldcg(&g_lg[(lane + 96) * BB + b]) : -CUDART_INF_F;
    float m = warp_max(fmaxf(fmaxf(v0, v1), fmaxf(v2, v3)));
    float s = expf(v0 - m) + expf(v1 - m) + expf(v2 - m) + (ok3 ? expf(v3 - m) : 0.f);
    s = warp_sum(s);
    float lse = m + logf(s);
    outp[lane]      = v0 - lse;
    outp[lane + 32] = v1 - lse;
    outp[lane + 64] = v2 - lse;
    if (ok3) outp[lane + 96] = v3 - lse;
}

__global__ void __launch_bounds__(NTH)
bahdanau_kernel(
    const float* __restrict__ enc,    const float* __restrict__ W_emb,
    const float* __restrict__ W_comb, const float* __restrict__ b_comb,
    const float* __restrict__ W_ih,   const float* __restrict__ W_hh,
    const float* __restrict__ b_ih,   const float* __restrict__ b_hh,
    const float* __restrict__ W_out,  const float* __restrict__ b_out,
    const float* __restrict__ w_vat,  const float* __restrict__ b_vat,
    const int* __restrict__ tgt, float* __restrict__ out)
{
    const int bid = blockIdx.x;
    const int tid = threadIdx.x;
    const int wid = tid >> 5;
    __shared__ SmemU sm;

    // zero initial hidden state
    for (int i = bid * NTH + tid; i < HH * BB; i += NB * NTH) g_hT[0][i] = 0.f;
    gridbar();

    for (int t = 0; t < TSTEPS; t++) {
        const float* hcur = g_hT[t & 1];
        float* hnext = g_hT[(t + 1) & 1];

        // ===== Phase A: attention | gh tiles 0-47 | raw prev logits =====
        if (bid < BB) {
            attention_block(&sm, bid, enc, w_vat, b_vat, hcur, g_ctxT);
        } else if (bid < 112) {
            int j0 = (bid - 64) * 16;
            gemm_tile(&sm, W_hh, HH, j0, G3H, 0, hcur, nullptr, nullptr,
                      nullptr, b_hh, g_gh);
        } else if (bid < 119 && t >= 1) {
            int j0 = (bid - 112) * 16;
            gemm_tile(&sm, W_out, HH, j0, VV, 0, hcur, nullptr, nullptr,
                      nullptr, b_out, g_lg);
        }
        gridbar();

        // ===== Phase B: comb halves | gh tiles 48-95 | log-softmax prev ====
        if (bid < BB) {
            int jt = bid >> 1, half = bid & 1;
            int j0 = jt * 16;
            if (half == 0) {
                gemm_tile(&sm, W_comb, 2 * HH, j0, HH, 1, W_emb, nullptr,
                          nullptr, tgt + t * BB, nullptr, g_xp[0]);
            } else {
                gemm_tile(&sm, W_comb + HH, 2 * HH, j0, HH, 0, g_ctxT, nullptr,
                          nullptr, nullptr, nullptr, g_xp[1]);
            }
        } else if (bid < 112) {
            int j0 = (bid - 64 + 48) * 16;
            gemm_tile(&sm, W_hh, HH, j0, G3H, 0, hcur, nullptr, nullptr,
                      nullptr, b_hh, g_gh);
        } else if (bid < 120 && t >= 1) {
            int b = (bid - 112) * 8 + wid;
            lsm_row(b, out + (size_t)b * TSTEPS * VV + (size_t)(t - 1) * VV);
        }
        gridbar();

        // ===== Phase C: gi tiles (x materialized in A-loader) =====
        if (bid < 96) {
            int j0 = bid * 16;
            gemm_tile(&sm, W_ih, HH, j0, G3H, 2, g_xp[0], g_xp[1], b_comb,
                      nullptr, b_ih, g_gi);
        }
        gridbar();

        // ===== Phase D: GRU gates elementwise =====
        {
            int e = bid * NTH + tid;
            if (e < HH * BB) {
                int i = e >> 6, b = e & 63;
                float gir = __ldcg(&g_gi[i * BB + b]);
                float giz = __ldcg(&g_gi[(i + HH) * BB + b]);
                float gin = __ldcg(&g_gi[(i + 2 * HH) * BB + b]);
                float ghr = __ldcg(&g_gh[i * BB + b]);
                float ghz = __ldcg(&g_gh[(i + HH) * BB + b]);
                float ghn = __ldcg(&g_gh[(i + 2 * HH) * BB + b]);
                float ho  = __ldcg(&hcur[i * BB + b]);
                float r = 1.f / (1.f + expf(-(gir + ghr)));
                float z = 1.f / (1.f + expf(-(giz + ghz)));
                float n = tanhf(gin + r * ghn);
                hnext[i * BB + b] = (1.f - z) * n + z * ho;
            }
        }
        gridbar();
    }

    // ===== final logits: slot TSTEPS-1 from h_T =====
    const float* hfin = g_hT[TSTEPS & 1];
    if (bid < 7) {
        int j0 = bid * 16;
        gemm_tile(&sm, W_out, HH, j0, VV, 0, hfin, nullptr, nullptr,
                  nullptr, b_out, g_lg);
    }
    gridbar();
    if (bid >= 112 && bid < 120) {
        int b = (bid - 112) * 8 + wid;
        lsm_row(b, out + (size_t)b * TSTEPS * VV + (size_t)(TSTEPS - 1) * VV);
    }
}

extern "C" void kernel_launch(void* const* d_in, const int* in_sizes, int n_in,
                              void* d_out, int out_size) {
    const float* enc    = (const float*)d_in[0];
    const float* W_emb  = (const float*)d_in[1];
    const float* W_comb = (const float*)d_in[2];
    const float* b_comb = (const float*)d_in[3];
    const float* W_ih   = (const float*)d_in[4];
    const float* W_hh   = (const float*)d_in[5];
    const float* b_ih   = (const float*)d_in[6];
    const float* b_hh   = (const float*)d_in[7];
    const float* W_out  = (const float*)d_in[8];
    const float* b_out  = (const float*)d_in[9];
    const float* w_vat  = (const float*)d_in[10];
    const float* b_vat  = (const float*)d_in[11];
    const int*   tgt    = (const int*)d_in[12];
    float* out = (float*)d_out;

    bahdanau_kernel<<<NB, NTH>>>(enc, W_emb, W_comb, b_comb, W_ih, W_hh,
                                 b_ih, b_hh, W_out, b_out, w_vat, b_vat,
                                 tgt, out);
}